// round 2
// baseline (speedup 1.0000x reference)
#include <cuda_runtime.h>
#include <cuda_bf16.h>

// One warp per edge: lane l loads float4 d=[4l,4l+4) of h[src] and h[dst],
// accumulates 4 products, butterfly-reduces across the warp, lane 0 writes.
// Indices are int32 (JAX x64 disabled downcasts jnp.int64 -> int32).
__global__ void __launch_bounds__(256) edge_dot_kernel(
    const float* __restrict__ h,
    const int* __restrict__ src,
    const int* __restrict__ dst,
    float* __restrict__ out,
    int n_edges)
{
    int warp_in_block = threadIdx.x >> 5;
    int lane = threadIdx.x & 31;
    int e = blockIdx.x * 8 + warp_in_block;
    if (e >= n_edges) return;

    int s = src[e];
    int d = dst[e];

    const float4* hs = reinterpret_cast<const float4*>(h + (long long)s * 128) + lane;
    const float4* hd = reinterpret_cast<const float4*>(h + (long long)d * 128) + lane;

    float4 a = __ldg(hs);
    float4 b = __ldg(hd);

    float acc = a.x * b.x;
    acc = fmaf(a.y, b.y, acc);
    acc = fmaf(a.z, b.z, acc);
    acc = fmaf(a.w, b.w, acc);

    // warp butterfly reduction
    #pragma unroll
    for (int m = 16; m > 0; m >>= 1)
        acc += __shfl_xor_sync(0xFFFFFFFFu, acc, m);

    if (lane == 0)
        out[e] = acc;
}

extern "C" void kernel_launch(void* const* d_in, const int* in_sizes, int n_in,
                              void* d_out, int out_size)
{
    const float* h   = (const float*)d_in[0];
    const int*   src = (const int*)d_in[1];
    const int*   dst = (const int*)d_in[2];
    float* out = (float*)d_out;

    int n_edges = in_sizes[1];          // E = 640000
    int edges_per_block = 8;            // 256 threads = 8 warps
    int grid = (n_edges + edges_per_block - 1) / edges_per_block;

    edge_dot_kernel<<<grid, 256>>>(h, src, dst, out, n_edges);
}

// round 3
// speedup vs baseline: 1.4841x; 1.4841x over previous
#include <cuda_runtime.h>
#include <cuda_bf16.h>

// 4 edges per warp: lanes 0-7 load the 8 indices (4 src + 4 dst), broadcast
// via shfl, then issue all 8 gather LDG.128s back-to-back (MLP=8/warp) before
// any reduction. Four butterfly reductions, then lane 0 writes one float4
// (out + e0 is 16B-aligned since e0 % 4 == 0).
__global__ void __launch_bounds__(256) edge_dot_kernel(
    const float* __restrict__ h,
    const int* __restrict__ src,
    const int* __restrict__ dst,
    float* __restrict__ out,
    int n_edges)
{
    const int warp_in_block = threadIdx.x >> 5;
    const int lane = threadIdx.x & 31;
    const int e0 = (blockIdx.x * 8 + warp_in_block) * 4;
    if (e0 >= n_edges) return;

    // lanes 0-3: src[e0+lane]; lanes 4-7: dst[e0+lane-4]
    int idx = 0;
    if (lane < 8) {
        int ei = e0 + (lane & 3);
        if (ei < n_edges)
            idx = (lane < 4) ? src[ei] : dst[ei];
    }
    const unsigned FULL = 0xFFFFFFFFu;
    int s0 = __shfl_sync(FULL, idx, 0);
    int s1 = __shfl_sync(FULL, idx, 1);
    int s2 = __shfl_sync(FULL, idx, 2);
    int s3 = __shfl_sync(FULL, idx, 3);
    int d0 = __shfl_sync(FULL, idx, 4);
    int d1 = __shfl_sync(FULL, idx, 5);
    int d2 = __shfl_sync(FULL, idx, 6);
    int d3 = __shfl_sync(FULL, idx, 7);

    // 8 independent 16B gathers, issued back-to-back.
    const float4* hb = reinterpret_cast<const float4*>(h);
    float4 a0 = __ldg(hb + (size_t)s0 * 32 + lane);
    float4 b0 = __ldg(hb + (size_t)d0 * 32 + lane);
    float4 a1 = __ldg(hb + (size_t)s1 * 32 + lane);
    float4 b1 = __ldg(hb + (size_t)d1 * 32 + lane);
    float4 a2 = __ldg(hb + (size_t)s2 * 32 + lane);
    float4 b2 = __ldg(hb + (size_t)d2 * 32 + lane);
    float4 a3 = __ldg(hb + (size_t)s3 * 32 + lane);
    float4 b3 = __ldg(hb + (size_t)d3 * 32 + lane);

    float acc0 = a0.x*b0.x; acc0 = fmaf(a0.y,b0.y,acc0); acc0 = fmaf(a0.z,b0.z,acc0); acc0 = fmaf(a0.w,b0.w,acc0);
    float acc1 = a1.x*b1.x; acc1 = fmaf(a1.y,b1.y,acc1); acc1 = fmaf(a1.z,b1.z,acc1); acc1 = fmaf(a1.w,b1.w,acc1);
    float acc2 = a2.x*b2.x; acc2 = fmaf(a2.y,b2.y,acc2); acc2 = fmaf(a2.z,b2.z,acc2); acc2 = fmaf(a2.w,b2.w,acc2);
    float acc3 = a3.x*b3.x; acc3 = fmaf(a3.y,b3.y,acc3); acc3 = fmaf(a3.z,b3.z,acc3); acc3 = fmaf(a3.w,b3.w,acc3);

    #pragma unroll
    for (int m = 16; m > 0; m >>= 1) {
        acc0 += __shfl_xor_sync(FULL, acc0, m);
        acc1 += __shfl_xor_sync(FULL, acc1, m);
        acc2 += __shfl_xor_sync(FULL, acc2, m);
        acc3 += __shfl_xor_sync(FULL, acc3, m);
    }

    if (lane == 0) {
        if (e0 + 3 < n_edges) {
            *reinterpret_cast<float4*>(out + e0) = make_float4(acc0, acc1, acc2, acc3);
        } else {
            float r[4] = {acc0, acc1, acc2, acc3};
            for (int i = 0; i < 4 && e0 + i < n_edges; i++) out[e0 + i] = r[i];
        }
    }
}

extern "C" void kernel_launch(void* const* d_in, const int* in_sizes, int n_in,
                              void* d_out, int out_size)
{
    const float* h   = (const float*)d_in[0];
    const int*   src = (const int*)d_in[1];
    const int*   dst = (const int*)d_in[2];
    float* out = (float*)d_out;

    int n_edges = in_sizes[1];               // E = 640000
    int edges_per_block = 32;                // 8 warps * 4 edges
    int grid = (n_edges + edges_per_block - 1) / edges_per_block;

    edge_dot_kernel<<<grid, 256>>>(h, src, dst, out, n_edges);
}

// round 4
// speedup vs baseline: 1.6419x; 1.1063x over previous
#include <cuda_runtime.h>
#include <cuda_bf16.h>

// 4 edges per warp, 8 lanes per edge.
// Lane l: group g = l>>3 (edge), sublane t = l&7.
// Each lane loads 4 float4 chunks (t, t+8, t+16, t+24) of h[src[g]] and
// h[dst[g]] -> 8 independent LDG.128, each instruction touching 4 contiguous
// 128B segments (same wavefront count as warp-wide row loads, but the
// reduction is only a 3-level butterfly within the 8-lane group, reducing
// all 4 edges simultaneously).
__global__ void __launch_bounds__(256) edge_dot_kernel(
    const float* __restrict__ h,
    const int* __restrict__ src,
    const int* __restrict__ dst,
    float* __restrict__ out,
    int n_edges)
{
    const int warp_in_block = threadIdx.x >> 5;
    const int lane = threadIdx.x & 31;
    const int g = lane >> 3;        // edge within warp (0..3)
    const int t = lane & 7;         // sublane within edge group
    const int e0 = (blockIdx.x * 8 + warp_in_block) * 4;
    if (e0 >= n_edges) return;

    const unsigned FULL = 0xFFFFFFFFu;

    // lanes 0-3: src[e0+lane]; lanes 4-7: dst[e0+lane-4]
    int idx = 0;
    if (lane < 8) {
        int ei = e0 + (lane & 3);
        if (ei < n_edges)
            idx = (lane < 4) ? src[ei] : dst[ei];
    }
    int s = __shfl_sync(FULL, idx, g);
    int d = __shfl_sync(FULL, idx, g + 4);

    const float4* ps = reinterpret_cast<const float4*>(h) + (size_t)s * 32;
    const float4* pd = reinterpret_cast<const float4*>(h) + (size_t)d * 32;

    // 8 independent 16B gathers (front-batched by ptxas -> MLP 8)
    float4 a0 = __ldg(ps + t);
    float4 a1 = __ldg(ps + t + 8);
    float4 a2 = __ldg(ps + t + 16);
    float4 a3 = __ldg(ps + t + 24);
    float4 b0 = __ldg(pd + t);
    float4 b1 = __ldg(pd + t + 8);
    float4 b2 = __ldg(pd + t + 16);
    float4 b3 = __ldg(pd + t + 24);

    float acc = a0.x * b0.x;
    acc = fmaf(a0.y, b0.y, acc); acc = fmaf(a0.z, b0.z, acc); acc = fmaf(a0.w, b0.w, acc);
    acc = fmaf(a1.x, b1.x, acc); acc = fmaf(a1.y, b1.y, acc);
    acc = fmaf(a1.z, b1.z, acc); acc = fmaf(a1.w, b1.w, acc);
    acc = fmaf(a2.x, b2.x, acc); acc = fmaf(a2.y, b2.y, acc);
    acc = fmaf(a2.z, b2.z, acc); acc = fmaf(a2.w, b2.w, acc);
    acc = fmaf(a3.x, b3.x, acc); acc = fmaf(a3.y, b3.y, acc);
    acc = fmaf(a3.z, b3.z, acc); acc = fmaf(a3.w, b3.w, acc);

    // 3-level butterfly within the 8-lane group (reduces 4 edges at once)
    acc += __shfl_xor_sync(FULL, acc, 4);
    acc += __shfl_xor_sync(FULL, acc, 2);
    acc += __shfl_xor_sync(FULL, acc, 1);

    // lanes 0,8,16,24 hold the 4 results -> one coalesced 16B STG.32
    if (t == 0 && e0 + g < n_edges)
        out[e0 + g] = acc;
}

extern "C" void kernel_launch(void* const* d_in, const int* in_sizes, int n_in,
                              void* d_out, int out_size)
{
    const float* h   = (const float*)d_in[0];
    const int*   src = (const int*)d_in[1];
    const int*   dst = (const int*)d_in[2];
    float* out = (float*)d_out;

    int n_edges = in_sizes[1];               // E = 640000
    int edges_per_block = 32;                // 8 warps * 4 edges
    int grid = (n_edges + edges_per_block - 1) / edges_per_block;

    edge_dot_kernel<<<grid, 256>>>(h, src, dst, out, n_edges);
}

// round 5
// speedup vs baseline: 1.7340x; 1.0561x over previous
#include <cuda_runtime.h>
#include <cuda_bf16.h>

// 8 edges per warp, 8 lanes per edge-group, 2 edges per group.
// Lane l: group g = l>>3, sublane t = l&7.
// Group g handles edges e0+2g (A) and e0+2g+1 (B). Each lane issues 16
// independent LDG.128 (4 chunks x {srcA,dstA,srcB,dstB}) -> MLP 16/warp.
// Two 3-level butterflies reduce both edges; lane t==0 stores a float2.
__global__ void __launch_bounds__(256) edge_dot_kernel(
    const float* __restrict__ h,
    const int* __restrict__ src,
    const int* __restrict__ dst,
    float* __restrict__ out,
    int n_edges)
{
    const int warp_in_block = threadIdx.x >> 5;
    const int lane = threadIdx.x & 31;
    const int g = lane >> 3;        // group (0..3)
    const int t = lane & 7;         // sublane in group
    const int e0 = (blockIdx.x * 8 + warp_in_block) * 8;
    if (e0 >= n_edges) return;

    const unsigned FULL = 0xFFFFFFFFu;

    // lanes 0-7: src[e0+lane]; lanes 8-15: dst[e0+lane-8]
    int idx = 0;
    if (lane < 16) {
        int ei = e0 + (lane & 7);
        if (ei < n_edges)
            idx = (lane < 8) ? src[ei] : dst[ei];
    }
    int sA = __shfl_sync(FULL, idx, 2 * g);
    int sB = __shfl_sync(FULL, idx, 2 * g + 1);
    int dA = __shfl_sync(FULL, idx, 8 + 2 * g);
    int dB = __shfl_sync(FULL, idx, 8 + 2 * g + 1);

    const float4* psA = reinterpret_cast<const float4*>(h) + (size_t)sA * 32 + t;
    const float4* pdA = reinterpret_cast<const float4*>(h) + (size_t)dA * 32 + t;
    const float4* psB = reinterpret_cast<const float4*>(h) + (size_t)sB * 32 + t;
    const float4* pdB = reinterpret_cast<const float4*>(h) + (size_t)dB * 32 + t;

    // 16 independent 16B gathers
    float4 a0 = __ldg(psA);      float4 a1 = __ldg(psA + 8);
    float4 a2 = __ldg(psA + 16); float4 a3 = __ldg(psA + 24);
    float4 b0 = __ldg(pdA);      float4 b1 = __ldg(pdA + 8);
    float4 b2 = __ldg(pdA + 16); float4 b3 = __ldg(pdA + 24);
    float4 c0 = __ldg(psB);      float4 c1 = __ldg(psB + 8);
    float4 c2 = __ldg(psB + 16); float4 c3 = __ldg(psB + 24);
    float4 e4 = __ldg(pdB);      float4 e1 = __ldg(pdB + 8);
    float4 e2 = __ldg(pdB + 16); float4 e3 = __ldg(pdB + 24);

    float accA = a0.x * b0.x;
    accA = fmaf(a0.y, b0.y, accA); accA = fmaf(a0.z, b0.z, accA); accA = fmaf(a0.w, b0.w, accA);
    accA = fmaf(a1.x, b1.x, accA); accA = fmaf(a1.y, b1.y, accA);
    accA = fmaf(a1.z, b1.z, accA); accA = fmaf(a1.w, b1.w, accA);
    accA = fmaf(a2.x, b2.x, accA); accA = fmaf(a2.y, b2.y, accA);
    accA = fmaf(a2.z, b2.z, accA); accA = fmaf(a2.w, b2.w, accA);
    accA = fmaf(a3.x, b3.x, accA); accA = fmaf(a3.y, b3.y, accA);
    accA = fmaf(a3.z, b3.z, accA); accA = fmaf(a3.w, b3.w, accA);

    float accB = c0.x * e4.x;
    accB = fmaf(c0.y, e4.y, accB); accB = fmaf(c0.z, e4.z, accB); accB = fmaf(c0.w, e4.w, accB);
    accB = fmaf(c1.x, e1.x, accB); accB = fmaf(c1.y, e1.y, accB);
    accB = fmaf(c1.z, e1.z, accB); accB = fmaf(c1.w, e1.w, accB);
    accB = fmaf(c2.x, e2.x, accB); accB = fmaf(c2.y, e2.y, accB);
    accB = fmaf(c2.z, e2.z, accB); accB = fmaf(c2.w, e2.w, accB);
    accB = fmaf(c3.x, e3.x, accB); accB = fmaf(c3.y, e3.y, accB);
    accB = fmaf(c3.z, e3.z, accB); accB = fmaf(c3.w, e3.w, accB);

    // 3-level butterflies within the 8-lane group
    accA += __shfl_xor_sync(FULL, accA, 4);
    accB += __shfl_xor_sync(FULL, accB, 4);
    accA += __shfl_xor_sync(FULL, accA, 2);
    accB += __shfl_xor_sync(FULL, accB, 2);
    accA += __shfl_xor_sync(FULL, accA, 1);
    accB += __shfl_xor_sync(FULL, accB, 1);

    // group leaders (lanes 0,8,16,24) store 2 results each -> one 32B sector
    if (t == 0) {
        int eA = e0 + 2 * g;
        if (eA + 1 < n_edges) {
            *reinterpret_cast<float2*>(out + eA) = make_float2(accA, accB);
        } else if (eA < n_edges) {
            out[eA] = accA;
        }
    }
}

extern "C" void kernel_launch(void* const* d_in, const int* in_sizes, int n_in,
                              void* d_out, int out_size)
{
    const float* h   = (const float*)d_in[0];
    const int*   src = (const int*)d_in[1];
    const int*   dst = (const int*)d_in[2];
    float* out = (float*)d_out;

    int n_edges = in_sizes[1];               // E = 640000
    int edges_per_block = 64;                // 8 warps * 8 edges
    int grid = (n_edges + edges_per_block - 1) / edges_per_block;

    edge_dot_kernel<<<grid, 256>>>(h, src, dst, out, n_edges);
}